// round 15
// baseline (speedup 1.0000x reference)
#include <cuda_runtime.h>
#include <cuda_fp16.h>
#include <math.h>
#include <stdint.h>

#define HDIM  1024
#define IDIM  2816
#define TWOI  5632
#define NEXP  8
#define NTOK  2048
#define NGRP  9   // 8 experts + base (group 8)

#define NSTG   4                // 4-stage cp.async pipeline (32 K each)
#define ABYTES 10240            // 128 rows x 40 halves x 2B (row stride 80B)
#define BROWB  272              // B smem row stride bytes (128 halves data + pad)
#define BBYTES (32 * BROWB)     // 8704
#define SMEM_BYTES (NSTG * (ABYTES + BBYTES))   // 75776 -> 2 CTAs/SM

// ---------------- scratch (device globals; no allocation) ----------------
__device__ int    g_cnt[NGRP];
__device__ int    g_tok[NGRP * NTOK];
__device__ int    g_te[NTOK * 2];
__device__ int    g_tp[NTOK * 2];
__device__ float  g_tw[NTOK * 2];
__device__ __half g_act[(size_t)NGRP * NTOK * IDIM];
__device__ float  g_y  [(size_t)NGRP * NTOK * HDIM];

// fp16 copies (converted once per launch; deterministic)
__device__ __half xh[NTOK * HDIM];
__device__ __half bwguh[HDIM * TWOI];
__device__ __half bwdh[IDIM * HDIM];
__device__ __half ewguh[(size_t)NEXP * HDIM * TWOI];
__device__ __half ewdh[(size_t)NEXP * IDIM * HDIM];

// ---------------- PTX helpers ----------------
__device__ __forceinline__ uint32_t h2u(__half2 h) { return *(uint32_t*)&h; }
__device__ __forceinline__ uint32_t sh_addr(const void* p) {
    return (uint32_t)__cvta_generic_to_shared(p);
}
#define MMA_F16(C, A, B)                                                      \
    asm volatile(                                                             \
        "mma.sync.aligned.m16n8k16.row.col.f32.f16.f16.f32 "                  \
        "{%0,%1,%2,%3}, {%4,%5,%6,%7}, {%8,%9}, {%0,%1,%2,%3};"               \
        : "+f"((C)[0]), "+f"((C)[1]), "+f"((C)[2]), "+f"((C)[3])              \
        : "r"((A)[0]), "r"((A)[1]), "r"((A)[2]), "r"((A)[3]),                 \
          "r"((B)[0]), "r"((B)[1]))
#define LDSM_X4(r0, r1, r2, r3, a)                                            \
    asm volatile("ldmatrix.sync.aligned.m8n8.x4.shared.b16 {%0,%1,%2,%3}, [%4];" \
                 : "=r"(r0), "=r"(r1), "=r"(r2), "=r"(r3) : "r"(a))
#define LDSM_X4T(r0, r1, r2, r3, a)                                           \
    asm volatile("ldmatrix.sync.aligned.m8n8.x4.trans.shared.b16 {%0,%1,%2,%3}, [%4];" \
                 : "=r"(r0), "=r"(r1), "=r"(r2), "=r"(r3) : "r"(a))
#define CP16(dst, src)                                                        \
    asm volatile("cp.async.cg.shared.global [%0], [%1], 16;" :: "r"(dst), "l"(src))
#define CP_COMMIT() asm volatile("cp.async.commit_group;" ::: "memory")
#define CP_WAIT2()  asm volatile("cp.async.wait_group 2;" ::: "memory")

// ---------------- init ----------------
__global__ void k_init() {
    if (threadIdx.x < NGRP)
        g_cnt[threadIdx.x] = (threadIdx.x == NEXP) ? NTOK : 0;
}

// ------- fused router (+x conversion) + fp32->fp16 convert (weights) -------
#define CVT_N1 (HDIM * TWOI / 8)          // base_wgu
#define CVT_N2 (IDIM * HDIM / 8)          // base_wd
#define CVT_N3 (NEXP * CVT_N1)            // exp_wgu
#define CVT_N4 (NEXP * CVT_N2)            // exp_wd
#define CVT_TOTAL ((size_t)CVT_N1 + CVT_N2 + CVT_N3 + CVT_N4)
#define ROUTER_BLOCKS 256
#define CVTR_BLOCKS (ROUTER_BLOCKS + (unsigned)((CVT_TOTAL + 255) / 256))

__global__ void k_cvt_router(const float* __restrict__ x, const float* __restrict__ gw,
                             const float* __restrict__ bwgu, const float* __restrict__ bwd,
                             const float* __restrict__ ewgu, const float* __restrict__ ewd) {
    if (blockIdx.x < ROUTER_BLOCKS) {
        int gtid = blockIdx.x * 256 + threadIdx.x;
        int t    = gtid >> 5;
        int lane = gtid & 31;

        const float* xr = x + (size_t)t * HDIM;
        __half* xhr = xh + (size_t)t * HDIM;
        float acc[NEXP];
#pragma unroll
        for (int e = 0; e < NEXP; e++) acc[e] = 0.f;
        for (int k = lane; k < HDIM; k += 32) {
            float xv = xr[k];
            xhr[k] = __float2half_rn(xv);
            const float4* gr = (const float4*)(gw + (size_t)k * NEXP);
            float4 g0 = gr[0], g1 = gr[1];
            acc[0] += xv * g0.x; acc[1] += xv * g0.y;
            acc[2] += xv * g0.z; acc[3] += xv * g0.w;
            acc[4] += xv * g1.x; acc[5] += xv * g1.y;
            acc[6] += xv * g1.z; acc[7] += xv * g1.w;
        }
#pragma unroll
        for (int e = 0; e < NEXP; e++) {
#pragma unroll
            for (int off = 16; off; off >>= 1)
                acc[e] += __shfl_xor_sync(0xffffffffu, acc[e], off);
        }
        if (lane == 0) {
            float m = acc[0];
#pragma unroll
            for (int e = 1; e < NEXP; e++) m = fmaxf(m, acc[e]);
            float p[NEXP];
#pragma unroll
            for (int e = 0; e < NEXP; e++) p[e] = expf(acc[e] - m);
            int i0 = 0; float b0 = p[0];
#pragma unroll
            for (int e = 1; e < NEXP; e++) if (p[e] > b0) { b0 = p[e]; i0 = e; }
            int i1 = (i0 == 0) ? 1 : 0; float b1 = p[i1];
#pragma unroll
            for (int e = 0; e < NEXP; e++)
                if (e != i0 && p[e] > b1) { b1 = p[e]; i1 = e; }
            float s = b0 + b1;
            int p0 = atomicAdd(&g_cnt[i0], 1);
            int p1 = atomicAdd(&g_cnt[i1], 1);
            g_tok[i0 * NTOK + p0] = t;
            g_tok[i1 * NTOK + p1] = t;
            g_te[2 * t + 0] = i0; g_tp[2 * t + 0] = p0; g_tw[2 * t + 0] = b0 / s;
            g_te[2 * t + 1] = i1; g_tp[2 * t + 1] = p1; g_tw[2 * t + 1] = b1 / s;
            g_tok[NEXP * NTOK + t] = t;
        }
        return;
    }
    size_t i = (size_t)(blockIdx.x - ROUTER_BLOCKS) * 256 + threadIdx.x;
    if (i >= CVT_TOTAL) return;
    const float* s; __half* d; size_t off;
    if (i < CVT_N1)                       { s = bwgu; d = bwguh; off = i; }
    else if (i < (size_t)CVT_N1 + CVT_N2) { s = bwd;  d = bwdh;  off = i - CVT_N1; }
    else if (i < (size_t)CVT_N1 + CVT_N2 + CVT_N3)
                                          { s = ewgu; d = ewguh; off = i - CVT_N1 - CVT_N2; }
    else                                  { s = ewd;  d = ewdh;  off = i - CVT_N1 - CVT_N2 - (size_t)CVT_N3; }
    float4 a = ((const float4*)s)[2 * off];
    float4 b = ((const float4*)s)[2 * off + 1];
    uint4 o;
    o.x = h2u(__floats2half2_rn(a.x, a.y));
    o.y = h2u(__floats2half2_rn(a.z, a.w));
    o.z = h2u(__floats2half2_rn(b.x, b.y));
    o.w = h2u(__floats2half2_rn(b.z, b.w));
    ((uint4*)d)[off] = o;
}

// ============================================================================
// GEMM1: act = silu(x@Wg) * (x@Wu). TWO m-blocks per CTA, continuous 64-stage
// pipeline (B reused L2-hot; block-0 epilogue overlaps block-1 fill).
// Block 128 rows x 64 act-cols. 4 warps, warp 64x64 B-cols.
// ============================================================================
__global__ __launch_bounds__(128, 2) void k_gemm1() {
    int g   = blockIdx.z;
    int cnt = g_cnt[g];
    int m0  = blockIdx.x * 256;
    if (m0 >= cnt) return;
    int n0  = blockIdx.y * 64;
    const __half* W = (g == NEXP) ? bwguh : (ewguh + (size_t)g * HDIM * TWOI);

    extern __shared__ char smraw[];
    uint32_t sb = sh_addr(smraw);
    __shared__ int stok[256];

    int tid = threadIdx.x, wid = tid >> 5, lane = tid & 31;
    int wm = wid & 1, wn = wid >> 1;
    int qg = lane >> 2, qq = lane & 3;

    {
        int r0 = m0 + tid;       stok[tid]       = g_tok[g * NTOK + ((r0 < cnt) ? r0 : cnt - 1)];
        int r1 = m0 + 128 + tid; stok[tid + 128] = g_tok[g * NTOK + ((r1 < cnt) ? r1 : cnt - 1)];
    }
    __syncthreads();

    int arow = tid >> 2, aq = tid & 3;
    const __half* asrc0[4];
    const __half* asrc1[4];
#pragma unroll
    for (int j = 0; j < 4; j++) {
        asrc0[j] = xh + (size_t)stok[arow + 32 * j] * HDIM + aq * 8;
        asrc1[j] = xh + (size_t)stok[128 + arow + 32 * j] * HDIM + aq * 8;
    }
    uint32_t adst = (uint32_t)(arow * 80 + aq * 16);
    int bk = tid >> 4, bnc = tid & 15;
    size_t bcol = (bnc < 8) ? (size_t)(n0 + bnc * 8)
                            : ((size_t)IDIM + n0 + (bnc - 8) * 8);
    const __half* bsrc = W + (size_t)bk * TWOI + bcol;
    uint32_t bdst = (uint32_t)(bk * BROWB + bnc * 16);

    uint32_t a_off = (uint32_t)((wm * 64 + (lane & 15)) * 80 + (lane >> 4) * 16);
    uint32_t b_off = (uint32_t)((lane & 15) * BROWB + (lane >> 4) * 16);

    float acc[4][8][4];
#pragma unroll
    for (int a = 0; a < 4; a++)
#pragma unroll
        for (int b = 0; b < 8; b++)
#pragma unroll
            for (int c = 0; c < 4; c++) acc[a][b][c] = 0.f;

    const bool two = (m0 + 128 < cnt);
    const int NSTOT = two ? 64 : 32;     // global stage count (32 per m-block)

    auto issueA = [&](int gs) {
        int kk = (gs & 31) * 32, sub = gs & 3;
        uint32_t Ab = sb + sub * ABYTES;
        const __half* const* ap = (gs & 32) ? asrc1 : asrc0;
#pragma unroll
        for (int j = 0; j < 4; j++) CP16(Ab + adst + j * (32 * 80), ap[j] + kk);
    };
    auto issueB = [&](int gs) {
        int kk = (gs & 31) * 32, sub = gs & 3;
        uint32_t Bb = sb + NSTG * ABYTES + sub * BBYTES;
#pragma unroll
        for (int j = 0; j < 4; j++)
            CP16(Bb + bdst + j * (8 * BROWB), bsrc + (size_t)(kk + 8 * j) * TWOI);
    };
    auto ldfrag = [&](int gs, int ks, uint32_t (&af)[4][4], uint32_t (&bf)[8][2]) {
        uint32_t Ab = sb + (gs & 3) * ABYTES;
        uint32_t Bb = sb + NSTG * ABYTES + (gs & 3) * BBYTES;
#pragma unroll
        for (int mt = 0; mt < 4; mt++)
            LDSM_X4(af[mt][0], af[mt][1], af[mt][2], af[mt][3],
                    Ab + a_off + mt * 1280 + ks * 32);
#pragma unroll
        for (int p = 0; p < 4; p++) {
            uint32_t na = (p < 2) ? (uint32_t)(wn * 32 + p * 16)
                                  : (uint32_t)(64 + wn * 32 + (p - 2) * 16);
            LDSM_X4T(bf[2 * p][0], bf[2 * p][1], bf[2 * p + 1][0], bf[2 * p + 1][1],
                     Bb + b_off + ks * (16 * BROWB) + na * 2);
        }
    };
    auto domma = [&](uint32_t (&af)[4][4], uint32_t (&bf)[8][2]) {
#pragma unroll
        for (int mt = 0; mt < 4; mt++)
#pragma unroll
            for (int nt = 0; nt < 8; nt++)
                MMA_F16(acc[mt][nt], af[mt], bf[nt]);
    };
    auto epilogue = [&](int mbase) {
#pragma unroll
        for (int mt = 0; mt < 4; mt++) {
            int r0 = mbase + wm * 64 + mt * 16 + qg;
#pragma unroll
            for (int nt = 0; nt < 4; nt++) {
                int c = n0 + wn * 32 + 8 * nt + 2 * qq;
                float gv0 = acc[mt][nt][0], gv1 = acc[mt][nt][1];
                float uv0 = acc[mt][nt + 4][0], uv1 = acc[mt][nt + 4][1];
                *(__half2*)&g_act[((size_t)g * NTOK + r0) * IDIM + c] =
                    __floats2half2_rn(uv0 * (gv0 / (1.f + expf(-gv0))),
                                      uv1 * (gv1 / (1.f + expf(-gv1))));
                float gv2 = acc[mt][nt][2], gv3 = acc[mt][nt][3];
                float uv2 = acc[mt][nt + 4][2], uv3 = acc[mt][nt + 4][3];
                *(__half2*)&g_act[((size_t)g * NTOK + r0 + 8) * IDIM + c] =
                    __floats2half2_rn(uv2 * (gv2 / (1.f + expf(-gv2))),
                                      uv3 * (gv3 / (1.f + expf(-gv3))));
            }
        }
    };

    issueA(0); issueB(0); CP_COMMIT();
    issueA(1); issueB(1); CP_COMMIT();
    issueA(2); issueB(2); CP_COMMIT();

    uint32_t afA[4][4], bfA[8][2], afB[4][4], bfB[8][2];
    CP_WAIT2();
    __syncthreads();
    ldfrag(0, 0, afA, bfA);

    for (int gs = 0; gs < NSTOT; gs++) {
        ldfrag(gs, 1, afB, bfB);
        if (gs + 3 < NSTOT) issueA(gs + 3);
        domma(afA, bfA);
        if (gs + 3 < NSTOT) issueB(gs + 3);
        CP_COMMIT();
        if (gs + 1 < NSTOT) {
            CP_WAIT2();
            __syncthreads();
            ldfrag(gs + 1, 0, afA, bfA);   // hidden under domma(afB,bfB)
        }
        domma(afB, bfB);
        if (gs == 31 && two) {
            // m-block 0 done: drain accumulators while block-1 cp.asyncs fly
            epilogue(m0);
#pragma unroll
            for (int a = 0; a < 4; a++)
#pragma unroll
                for (int b = 0; b < 8; b++)
#pragma unroll
                    for (int c = 0; c < 4; c++) acc[a][b][c] = 0.f;
        }
    }
    epilogue(two ? (m0 + 128) : m0);
}

// ============================================================================
// GEMM2: y = act(half) @ Wd. Unchanged (98us / tensor 65%). Grid x = m-tiles.
// ============================================================================
__global__ __launch_bounds__(128, 2) void k_gemm2() {
    int g   = blockIdx.z;
    int cnt = g_cnt[g];
    int m0  = blockIdx.x * 128;
    if (m0 >= cnt) return;
    int n0  = blockIdx.y * 128;
    const __half* W = (g == NEXP) ? bwdh : (ewdh + (size_t)g * IDIM * HDIM);

    extern __shared__ char smraw[];
    uint32_t sb = sh_addr(smraw);

    int tid = threadIdx.x, wid = tid >> 5, lane = tid & 31;
    int wm = wid & 1, wn = wid >> 1;
    int qg = lane >> 2, qq = lane & 3;

    int arow = tid >> 2, aq = tid & 3;
    const __half* asrc = g_act + ((size_t)g * NTOK + m0 + arow) * IDIM + aq * 8;
    uint32_t adst = (uint32_t)(arow * 80 + aq * 16);
    int bk = tid >> 4, bnc = tid & 15;
    const __half* bsrc = W + (size_t)bk * HDIM + n0 + bnc * 8;
    uint32_t bdst = (uint32_t)(bk * BROWB + bnc * 16);

    uint32_t a_off = (uint32_t)((wm * 64 + (lane & 15)) * 80 + (lane >> 4) * 16);
    uint32_t b_off = (uint32_t)((lane & 15) * BROWB + (lane >> 4) * 16);

    float acc[4][8][4];
#pragma unroll
    for (int a = 0; a < 4; a++)
#pragma unroll
        for (int b = 0; b < 8; b++)
#pragma unroll
            for (int c = 0; c < 4; c++) acc[a][b][c] = 0.f;

    auto issueA = [&](int s) {
        int kk = s * 32, sub = s & 3;
        uint32_t Ab = sb + sub * ABYTES;
#pragma unroll
        for (int j = 0; j < 4; j++)
            CP16(Ab + adst + j * (32 * 80), asrc + (size_t)(32 * j) * IDIM + kk);
    };
    auto issueB = [&](int s) {
        int kk = s * 32, sub = s & 3;
        uint32_t Bb = sb + NSTG * ABYTES + sub * BBYTES;
#pragma unroll
        for (int j = 0; j < 4; j++)
            CP16(Bb + bdst + j * (8 * BROWB), bsrc + (size_t)(kk + 8 * j) * HDIM);
    };
    auto ldfrag = [&](int s, int ks, uint32_t (&af)[4][4], uint32_t (&bf)[8][2]) {
        uint32_t Ab = sb + (s & 3) * ABYTES;
        uint32_t Bb = sb + NSTG * ABYTES + (s & 3) * BBYTES;
#pragma unroll
        for (int mt = 0; mt < 4; mt++)
            LDSM_X4(af[mt][0], af[mt][1], af[mt][2], af[mt][3],
                    Ab + a_off + mt * 1280 + ks * 32);
#pragma unroll
        for (int p = 0; p < 4; p++) {
            uint32_t na = (uint32_t)(wn * 64 + p * 16);
            LDSM_X4T(bf[2 * p][0], bf[2 * p][1], bf[2 * p + 1][0], bf[2 * p + 1][1],
                     Bb + b_off + ks * (16 * BROWB) + na * 2);
        }
    };
    auto domma = [&](uint32_t (&af)[4][4], uint32_t (&bf)[8][2]) {
#pragma unroll
        for (int mt = 0; mt < 4; mt++)
#pragma unroll
            for (int nt = 0; nt < 8; nt++)
                MMA_F16(acc[mt][nt], af[mt], bf[nt]);
    };

    issueA(0); issueB(0); CP_COMMIT();
    issueA(1); issueB(1); CP_COMMIT();
    issueA(2); issueB(2); CP_COMMIT();

    uint32_t afA[4][4], bfA[8][2], afB[4][4], bfB[8][2];
    CP_WAIT2();
    __syncthreads();
    ldfrag(0, 0, afA, bfA);

    const int NST = IDIM / 32;   // 88
    for (int s = 0; s < NST; s++) {
        ldfrag(s, 1, afB, bfB);
        if (s + 3 < NST) issueA(s + 3);
        domma(afA, bfA);
        if (s + 3 < NST) issueB(s + 3);
        CP_COMMIT();
        if (s + 1 < NST) {
            CP_WAIT2();
            __syncthreads();
            ldfrag(s + 1, 0, afA, bfA);
        }
        domma(afB, bfB);
    }

#pragma unroll
    for (int mt = 0; mt < 4; mt++) {
        int r0 = m0 + wm * 64 + mt * 16 + qg;
#pragma unroll
        for (int nt = 0; nt < 8; nt++) {
            int c = n0 + wn * 64 + 8 * nt + 2 * qq;
            *(float2*)&g_y[((size_t)g * NTOK + r0) * HDIM + c] =
                make_float2(acc[mt][nt][0], acc[mt][nt][1]);
            *(float2*)&g_y[((size_t)g * NTOK + r0 + 8) * HDIM + c] =
                make_float2(acc[mt][nt][2], acc[mt][nt][3]);
        }
    }
}

// ---------------- combine ----------------
__global__ void k_combine(float* __restrict__ out) {
    int idx = blockIdx.x * blockDim.x + threadIdx.x;
    int t  = idx >> 8;
    int h4 = (idx & 255) << 2;
    if (t >= NTOK) return;

    int   e0 = g_te[2 * t + 0], p0 = g_tp[2 * t + 0];
    int   e1 = g_te[2 * t + 1], p1 = g_tp[2 * t + 1];
    float w0 = g_tw[2 * t + 0], w1 = g_tw[2 * t + 1];

    float4 yb = *(const float4*)&g_y[((size_t)NEXP * NTOK + t ) * HDIM + h4];
    float4 y0 = *(const float4*)&g_y[((size_t)e0   * NTOK + p0) * HDIM + h4];
    float4 y1 = *(const float4*)&g_y[((size_t)e1   * NTOK + p1) * HDIM + h4];

    float4 o;
    o.x = yb.x + w0 * y0.x + w1 * y1.x;
    o.y = yb.y + w0 * y0.y + w1 * y1.y;
    o.z = yb.z + w0 * y0.z + w1 * y1.z;
    o.w = yb.w + w0 * y0.w + w1 * y1.w;
    *(float4*)&out[(size_t)t * HDIM + h4] = o;
}

// ---------------- launch ----------------
extern "C" void kernel_launch(void* const* d_in, const int* in_sizes, int n_in,
                              void* d_out, int out_size) {
    const float* x        = (const float*)d_in[0];
    const float* gate_w   = (const float*)d_in[1];
    const float* base_wgu = (const float*)d_in[2];
    const float* base_wd  = (const float*)d_in[3];
    const float* exp_wgu  = (const float*)d_in[4];
    const float* exp_wd   = (const float*)d_in[5];
    float* out = (float*)d_out;

    cudaFuncSetAttribute(k_gemm1, cudaFuncAttributeMaxDynamicSharedMemorySize, SMEM_BYTES);
    cudaFuncSetAttribute(k_gemm2, cudaFuncAttributeMaxDynamicSharedMemorySize, SMEM_BYTES);

    k_init<<<1, 32>>>();
    k_cvt_router<<<CVTR_BLOCKS, 256>>>(x, gate_w, base_wgu, base_wd, exp_wgu, exp_wd);
    k_gemm1<<<dim3(NTOK / 256, IDIM / 64, NGRP), 128, SMEM_BYTES>>>();
    k_gemm2<<<dim3(NTOK / 128, HDIM / 128, NGRP), 128, SMEM_BYTES>>>();
    k_combine<<<(NTOK * (HDIM / 4)) / 256, 256>>>(out);
}

// round 16
// speedup vs baseline: 1.0929x; 1.0929x over previous
#include <cuda_runtime.h>
#include <cuda_fp16.h>
#include <math.h>
#include <stdint.h>

#define HDIM  1024
#define IDIM  2816
#define TWOI  5632
#define NEXP  8
#define NTOK  2048
#define NGRP  9   // 8 experts + base (group 8)

#define NSTG   4                // 4-stage cp.async pipeline (32 K each)
#define ABYTES 10240            // 128 rows x 40 halves x 2B (row stride 80B)
#define BROWB  272              // B smem row stride bytes (128 halves data + pad)
#define BBYTES (32 * BROWB)     // 8704
#define SMEM_BYTES (NSTG * (ABYTES + BBYTES))   // 75776 -> 2 CTAs/SM

// ---------------- scratch (device globals; no allocation) ----------------
__device__ int    g_cnt[NGRP];
__device__ int    g_tok[NGRP * NTOK];
__device__ int    g_te[NTOK * 2];
__device__ int    g_tp[NTOK * 2];
__device__ float  g_tw[NTOK * 2];
__device__ __half g_act[(size_t)NGRP * NTOK * IDIM];
__device__ float  g_y  [(size_t)NGRP * NTOK * HDIM];

// fp16 copies (converted once per launch; deterministic)
__device__ __half xh[NTOK * HDIM];
__device__ __half bwguh[HDIM * TWOI];
__device__ __half bwdh[IDIM * HDIM];
__device__ __half ewguh[(size_t)NEXP * HDIM * TWOI];
__device__ __half ewdh[(size_t)NEXP * IDIM * HDIM];

// ---------------- PTX helpers ----------------
__device__ __forceinline__ uint32_t h2u(__half2 h) { return *(uint32_t*)&h; }
__device__ __forceinline__ uint32_t sh_addr(const void* p) {
    return (uint32_t)__cvta_generic_to_shared(p);
}
#define MMA_F16(C, A, B)                                                      \
    asm volatile(                                                             \
        "mma.sync.aligned.m16n8k16.row.col.f32.f16.f16.f32 "                  \
        "{%0,%1,%2,%3}, {%4,%5,%6,%7}, {%8,%9}, {%0,%1,%2,%3};"               \
        : "+f"((C)[0]), "+f"((C)[1]), "+f"((C)[2]), "+f"((C)[3])              \
        : "r"((A)[0]), "r"((A)[1]), "r"((A)[2]), "r"((A)[3]),                 \
          "r"((B)[0]), "r"((B)[1]))
#define LDSM_X4(r0, r1, r2, r3, a)                                            \
    asm volatile("ldmatrix.sync.aligned.m8n8.x4.shared.b16 {%0,%1,%2,%3}, [%4];" \
                 : "=r"(r0), "=r"(r1), "=r"(r2), "=r"(r3) : "r"(a))
#define LDSM_X4T(r0, r1, r2, r3, a)                                           \
    asm volatile("ldmatrix.sync.aligned.m8n8.x4.trans.shared.b16 {%0,%1,%2,%3}, [%4];" \
                 : "=r"(r0), "=r"(r1), "=r"(r2), "=r"(r3) : "r"(a))
#define CP16(dst, src)                                                        \
    asm volatile("cp.async.cg.shared.global [%0], [%1], 16;" :: "r"(dst), "l"(src))
#define CP_COMMIT() asm volatile("cp.async.commit_group;" ::: "memory")
#define CP_WAIT2()  asm volatile("cp.async.wait_group 2;" ::: "memory")

// ---------------- init ----------------
__global__ void k_init() {
    if (threadIdx.x < NGRP)
        g_cnt[threadIdx.x] = (threadIdx.x == NEXP) ? NTOK : 0;
}

// ------- fused router (+x conversion) + fp32->fp16 convert (weights) -------
#define CVT_N1 (HDIM * TWOI / 8)          // base_wgu
#define CVT_N2 (IDIM * HDIM / 8)          // base_wd
#define CVT_N3 (NEXP * CVT_N1)            // exp_wgu
#define CVT_N4 (NEXP * CVT_N2)            // exp_wd
#define CVT_TOTAL ((size_t)CVT_N1 + CVT_N2 + CVT_N3 + CVT_N4)
#define ROUTER_BLOCKS 256
#define CVTR_BLOCKS (ROUTER_BLOCKS + (unsigned)((CVT_TOTAL + 255) / 256))

__global__ void k_cvt_router(const float* __restrict__ x, const float* __restrict__ gw,
                             const float* __restrict__ bwgu, const float* __restrict__ bwd,
                             const float* __restrict__ ewgu, const float* __restrict__ ewd) {
    if (blockIdx.x < ROUTER_BLOCKS) {
        int gtid = blockIdx.x * 256 + threadIdx.x;
        int t    = gtid >> 5;
        int lane = gtid & 31;

        const float* xr = x + (size_t)t * HDIM;
        __half* xhr = xh + (size_t)t * HDIM;
        float acc[NEXP];
#pragma unroll
        for (int e = 0; e < NEXP; e++) acc[e] = 0.f;
        for (int k = lane; k < HDIM; k += 32) {
            float xv = xr[k];
            xhr[k] = __float2half_rn(xv);
            const float4* gr = (const float4*)(gw + (size_t)k * NEXP);
            float4 g0 = gr[0], g1 = gr[1];
            acc[0] += xv * g0.x; acc[1] += xv * g0.y;
            acc[2] += xv * g0.z; acc[3] += xv * g0.w;
            acc[4] += xv * g1.x; acc[5] += xv * g1.y;
            acc[6] += xv * g1.z; acc[7] += xv * g1.w;
        }
#pragma unroll
        for (int e = 0; e < NEXP; e++) {
#pragma unroll
            for (int off = 16; off; off >>= 1)
                acc[e] += __shfl_xor_sync(0xffffffffu, acc[e], off);
        }
        if (lane == 0) {
            float m = acc[0];
#pragma unroll
            for (int e = 1; e < NEXP; e++) m = fmaxf(m, acc[e]);
            float p[NEXP];
#pragma unroll
            for (int e = 0; e < NEXP; e++) p[e] = expf(acc[e] - m);
            int i0 = 0; float b0 = p[0];
#pragma unroll
            for (int e = 1; e < NEXP; e++) if (p[e] > b0) { b0 = p[e]; i0 = e; }
            int i1 = (i0 == 0) ? 1 : 0; float b1 = p[i1];
#pragma unroll
            for (int e = 0; e < NEXP; e++)
                if (e != i0 && p[e] > b1) { b1 = p[e]; i1 = e; }
            float s = b0 + b1;
            int p0 = atomicAdd(&g_cnt[i0], 1);
            int p1 = atomicAdd(&g_cnt[i1], 1);
            g_tok[i0 * NTOK + p0] = t;
            g_tok[i1 * NTOK + p1] = t;
            g_te[2 * t + 0] = i0; g_tp[2 * t + 0] = p0; g_tw[2 * t + 0] = b0 / s;
            g_te[2 * t + 1] = i1; g_tp[2 * t + 1] = p1; g_tw[2 * t + 1] = b1 / s;
            g_tok[NEXP * NTOK + t] = t;
        }
        return;
    }
    size_t i = (size_t)(blockIdx.x - ROUTER_BLOCKS) * 256 + threadIdx.x;
    if (i >= CVT_TOTAL) return;
    const float* s; __half* d; size_t off;
    if (i < CVT_N1)                       { s = bwgu; d = bwguh; off = i; }
    else if (i < (size_t)CVT_N1 + CVT_N2) { s = bwd;  d = bwdh;  off = i - CVT_N1; }
    else if (i < (size_t)CVT_N1 + CVT_N2 + CVT_N3)
                                          { s = ewgu; d = ewguh; off = i - CVT_N1 - CVT_N2; }
    else                                  { s = ewd;  d = ewdh;  off = i - CVT_N1 - CVT_N2 - (size_t)CVT_N3; }
    float4 a = ((const float4*)s)[2 * off];
    float4 b = ((const float4*)s)[2 * off + 1];
    uint4 o;
    o.x = h2u(__floats2half2_rn(a.x, a.y));
    o.y = h2u(__floats2half2_rn(a.z, a.w));
    o.z = h2u(__floats2half2_rn(b.x, b.y));
    o.w = h2u(__floats2half2_rn(b.z, b.w));
    ((uint4*)d)[off] = o;
}

// ============================================================================
// GEMM1: act = silu(x@Wg) * (x@Wu). 4-stage cp.async, cross-stage frag pipe,
// issueA hoisted to loop top, unroll 2. Block 128 rows x 64 act-cols.
// 4 warps, warp 64x64 B-cols. Grid x = m-tiles.
// ============================================================================
__global__ __launch_bounds__(128, 2) void k_gemm1() {
    int g   = blockIdx.z;
    int cnt = g_cnt[g];
    int m0  = blockIdx.x * 128;
    if (m0 >= cnt) return;
    int n0  = blockIdx.y * 64;
    const __half* W = (g == NEXP) ? bwguh : (ewguh + (size_t)g * HDIM * TWOI);

    extern __shared__ char smraw[];
    uint32_t sb = sh_addr(smraw);
    __shared__ int stok[128];

    int tid = threadIdx.x, wid = tid >> 5, lane = tid & 31;
    int wm = wid & 1, wn = wid >> 1;
    int qg = lane >> 2, qq = lane & 3;

    { int r = m0 + tid; stok[tid] = g_tok[g * NTOK + ((r < cnt) ? r : cnt - 1)]; }
    __syncthreads();

    int arow = tid >> 2, aq = tid & 3;
    const __half* asrc[4];
#pragma unroll
    for (int j = 0; j < 4; j++)
        asrc[j] = xh + (size_t)stok[arow + 32 * j] * HDIM + aq * 8;
    uint32_t adst = (uint32_t)(arow * 80 + aq * 16);
    int bk = tid >> 4, bnc = tid & 15;
    size_t bcol = (bnc < 8) ? (size_t)(n0 + bnc * 8)
                            : ((size_t)IDIM + n0 + (bnc - 8) * 8);
    const __half* bsrc = W + (size_t)bk * TWOI + bcol;
    uint32_t bdst = (uint32_t)(bk * BROWB + bnc * 16);

    uint32_t a_off = (uint32_t)((wm * 64 + (lane & 15)) * 80 + (lane >> 4) * 16);
    uint32_t b_off = (uint32_t)((lane & 15) * BROWB + (lane >> 4) * 16);

    float acc[4][8][4];
#pragma unroll
    for (int a = 0; a < 4; a++)
#pragma unroll
        for (int b = 0; b < 8; b++)
#pragma unroll
            for (int c = 0; c < 4; c++) acc[a][b][c] = 0.f;

    auto issueA = [&](int s) {
        int kk = s * 32, sub = s & 3;
        uint32_t Ab = sb + sub * ABYTES;
#pragma unroll
        for (int j = 0; j < 4; j++) CP16(Ab + adst + j * (32 * 80), asrc[j] + kk);
    };
    auto issueB = [&](int s) {
        int kk = s * 32, sub = s & 3;
        uint32_t Bb = sb + NSTG * ABYTES + sub * BBYTES;
#pragma unroll
        for (int j = 0; j < 4; j++)
            CP16(Bb + bdst + j * (8 * BROWB), bsrc + (size_t)(kk + 8 * j) * TWOI);
    };
    auto ldfrag = [&](int s, int ks, uint32_t (&af)[4][4], uint32_t (&bf)[8][2]) {
        uint32_t Ab = sb + (s & 3) * ABYTES;
        uint32_t Bb = sb + NSTG * ABYTES + (s & 3) * BBYTES;
#pragma unroll
        for (int mt = 0; mt < 4; mt++)
            LDSM_X4(af[mt][0], af[mt][1], af[mt][2], af[mt][3],
                    Ab + a_off + mt * 1280 + ks * 32);
#pragma unroll
        for (int p = 0; p < 4; p++) {
            uint32_t na = (p < 2) ? (uint32_t)(wn * 32 + p * 16)
                                  : (uint32_t)(64 + wn * 32 + (p - 2) * 16);
            LDSM_X4T(bf[2 * p][0], bf[2 * p][1], bf[2 * p + 1][0], bf[2 * p + 1][1],
                     Bb + b_off + ks * (16 * BROWB) + na * 2);
        }
    };
    auto domma = [&](uint32_t (&af)[4][4], uint32_t (&bf)[8][2]) {
#pragma unroll
        for (int mt = 0; mt < 4; mt++)
#pragma unroll
            for (int nt = 0; nt < 8; nt++)
                MMA_F16(acc[mt][nt], af[mt], bf[nt]);
    };

    issueA(0); issueB(0); CP_COMMIT();
    issueA(1); issueB(1); CP_COMMIT();
    issueA(2); issueB(2); CP_COMMIT();

    uint32_t afA[4][4], bfA[8][2], afB[4][4], bfB[8][2];
    CP_WAIT2();
    __syncthreads();
    ldfrag(0, 0, afA, bfA);

    const int NST = HDIM / 32;   // 32
#pragma unroll 2
    for (int s = 0; s < NST; s++) {
        if (s + 3 < NST) issueA(s + 3);       // hoisted: CPs in flight early
        ldfrag(s, 1, afB, bfB);
        domma(afA, bfA);
        if (s + 3 < NST) issueB(s + 3);
        CP_COMMIT();
        if (s + 1 < NST) {
            CP_WAIT2();
            __syncthreads();
            ldfrag(s + 1, 0, afA, bfA);       // hidden under domma(afB,bfB)
        }
        domma(afB, bfB);
    }

    // epilogue: SwiGLU (gate = nt 0-3, up = nt 4-7 at same act cols)
#pragma unroll
    for (int mt = 0; mt < 4; mt++) {
        int r0 = m0 + wm * 64 + mt * 16 + qg;
#pragma unroll
        for (int nt = 0; nt < 4; nt++) {
            int c = n0 + wn * 32 + 8 * nt + 2 * qq;
            float gv0 = acc[mt][nt][0], gv1 = acc[mt][nt][1];
            float uv0 = acc[mt][nt + 4][0], uv1 = acc[mt][nt + 4][1];
            *(__half2*)&g_act[((size_t)g * NTOK + r0) * IDIM + c] =
                __floats2half2_rn(uv0 * (gv0 / (1.f + expf(-gv0))),
                                  uv1 * (gv1 / (1.f + expf(-gv1))));
            float gv2 = acc[mt][nt][2], gv3 = acc[mt][nt][3];
            float uv2 = acc[mt][nt + 4][2], uv3 = acc[mt][nt + 4][3];
            *(__half2*)&g_act[((size_t)g * NTOK + r0 + 8) * IDIM + c] =
                __floats2half2_rn(uv2 * (gv2 / (1.f + expf(-gv2))),
                                  uv3 * (gv3 / (1.f + expf(-gv3))));
        }
    }
}

// ============================================================================
// GEMM2: y = act(half) @ Wd. Same pipeline (issueA hoisted, unroll 2).
// Block 128x128, 4 warps, warp 64x64. Grid x = m-tiles.
// ============================================================================
__global__ __launch_bounds__(128, 2) void k_gemm2() {
    int g   = blockIdx.z;
    int cnt = g_cnt[g];
    int m0  = blockIdx.x * 128;
    if (m0 >= cnt) return;
    int n0  = blockIdx.y * 128;
    const __half* W = (g == NEXP) ? bwdh : (ewdh + (size_t)g * IDIM * HDIM);

    extern __shared__ char smraw[];
    uint32_t sb = sh_addr(smraw);

    int tid = threadIdx.x, wid = tid >> 5, lane = tid & 31;
    int wm = wid & 1, wn = wid >> 1;
    int qg = lane >> 2, qq = lane & 3;

    int arow = tid >> 2, aq = tid & 3;
    const __half* asrc = g_act + ((size_t)g * NTOK + m0 + arow) * IDIM + aq * 8;
    uint32_t adst = (uint32_t)(arow * 80 + aq * 16);
    int bk = tid >> 4, bnc = tid & 15;
    const __half* bsrc = W + (size_t)bk * HDIM + n0 + bnc * 8;
    uint32_t bdst = (uint32_t)(bk * BROWB + bnc * 16);

    uint32_t a_off = (uint32_t)((wm * 64 + (lane & 15)) * 80 + (lane >> 4) * 16);
    uint32_t b_off = (uint32_t)((lane & 15) * BROWB + (lane >> 4) * 16);

    float acc[4][8][4];
#pragma unroll
    for (int a = 0; a < 4; a++)
#pragma unroll
        for (int b = 0; b < 8; b++)
#pragma unroll
            for (int c = 0; c < 4; c++) acc[a][b][c] = 0.f;

    auto issueA = [&](int s) {
        int kk = s * 32, sub = s & 3;
        uint32_t Ab = sb + sub * ABYTES;
#pragma unroll
        for (int j = 0; j < 4; j++)
            CP16(Ab + adst + j * (32 * 80), asrc + (size_t)(32 * j) * IDIM + kk);
    };
    auto issueB = [&](int s) {
        int kk = s * 32, sub = s & 3;
        uint32_t Bb = sb + NSTG * ABYTES + sub * BBYTES;
#pragma unroll
        for (int j = 0; j < 4; j++)
            CP16(Bb + bdst + j * (8 * BROWB), bsrc + (size_t)(kk + 8 * j) * HDIM);
    };
    auto ldfrag = [&](int s, int ks, uint32_t (&af)[4][4], uint32_t (&bf)[8][2]) {
        uint32_t Ab = sb + (s & 3) * ABYTES;
        uint32_t Bb = sb + NSTG * ABYTES + (s & 3) * BBYTES;
#pragma unroll
        for (int mt = 0; mt < 4; mt++)
            LDSM_X4(af[mt][0], af[mt][1], af[mt][2], af[mt][3],
                    Ab + a_off + mt * 1280 + ks * 32);
#pragma unroll
        for (int p = 0; p < 4; p++) {
            uint32_t na = (uint32_t)(wn * 64 + p * 16);
            LDSM_X4T(bf[2 * p][0], bf[2 * p][1], bf[2 * p + 1][0], bf[2 * p + 1][1],
                     Bb + b_off + ks * (16 * BROWB) + na * 2);
        }
    };
    auto domma = [&](uint32_t (&af)[4][4], uint32_t (&bf)[8][2]) {
#pragma unroll
        for (int mt = 0; mt < 4; mt++)
#pragma unroll
            for (int nt = 0; nt < 8; nt++)
                MMA_F16(acc[mt][nt], af[mt], bf[nt]);
    };

    issueA(0); issueB(0); CP_COMMIT();
    issueA(1); issueB(1); CP_COMMIT();
    issueA(2); issueB(2); CP_COMMIT();

    uint32_t afA[4][4], bfA[8][2], afB[4][4], bfB[8][2];
    CP_WAIT2();
    __syncthreads();
    ldfrag(0, 0, afA, bfA);

    const int NST = IDIM / 32;   // 88
#pragma unroll 2
    for (int s = 0; s < NST; s++) {
        if (s + 3 < NST) issueA(s + 3);       // hoisted
        ldfrag(s, 1, afB, bfB);
        domma(afA, bfA);
        if (s + 3 < NST) issueB(s + 3);
        CP_COMMIT();
        if (s + 1 < NST) {
            CP_WAIT2();
            __syncthreads();
            ldfrag(s + 1, 0, afA, bfA);
        }
        domma(afB, bfB);
    }

#pragma unroll
    for (int mt = 0; mt < 4; mt++) {
        int r0 = m0 + wm * 64 + mt * 16 + qg;
#pragma unroll
        for (int nt = 0; nt < 8; nt++) {
            int c = n0 + wn * 64 + 8 * nt + 2 * qq;
            *(float2*)&g_y[((size_t)g * NTOK + r0) * HDIM + c] =
                make_float2(acc[mt][nt][0], acc[mt][nt][1]);
            *(float2*)&g_y[((size_t)g * NTOK + r0 + 8) * HDIM + c] =
                make_float2(acc[mt][nt][2], acc[mt][nt][3]);
        }
    }
}

// ---------------- combine ----------------
__global__ void k_combine(float* __restrict__ out) {
    int idx = blockIdx.x * blockDim.x + threadIdx.x;
    int t  = idx >> 8;
    int h4 = (idx & 255) << 2;
    if (t >= NTOK) return;

    int   e0 = g_te[2 * t + 0], p0 = g_tp[2 * t + 0];
    int   e1 = g_te[2 * t + 1], p1 = g_tp[2 * t + 1];
    float w0 = g_tw[2 * t + 0], w1 = g_tw[2 * t + 1];

    float4 yb = *(const float4*)&g_y[((size_t)NEXP * NTOK + t ) * HDIM + h4];
    float4 y0 = *(const float4*)&g_y[((size_t)e0   * NTOK + p0) * HDIM + h4];
    float4 y1 = *(const float4*)&g_y[((size_t)e1   * NTOK + p1) * HDIM + h4];

    float4 o;
    o.x = yb.x + w0 * y0.x + w1 * y1.x;
    o.y = yb.y + w0 * y0.y + w1 * y1.y;
    o.z = yb.z + w0 * y0.z + w1 * y1.z;
    o.w = yb.w + w0 * y0.w + w1 * y1.w;
    *(float4*)&out[(size_t)t * HDIM + h4] = o;
}

// ---------------- launch ----------------
extern "C" void kernel_launch(void* const* d_in, const int* in_sizes, int n_in,
                              void* d_out, int out_size) {
    const float* x        = (const float*)d_in[0];
    const float* gate_w   = (const float*)d_in[1];
    const float* base_wgu = (const float*)d_in[2];
    const float* base_wd  = (const float*)d_in[3];
    const float* exp_wgu  = (const float*)d_in[4];
    const float* exp_wd   = (const float*)d_in[5];
    float* out = (float*)d_out;

    cudaFuncSetAttribute(k_gemm1, cudaFuncAttributeMaxDynamicSharedMemorySize, SMEM_BYTES);
    cudaFuncSetAttribute(k_gemm2, cudaFuncAttributeMaxDynamicSharedMemorySize, SMEM_BYTES);

    k_init<<<1, 32>>>();
    k_cvt_router<<<CVTR_BLOCKS, 256>>>(x, gate_w, base_wgu, base_wd, exp_wgu, exp_wd);
    k_gemm1<<<dim3(NTOK / 128, IDIM / 64, NGRP), 128, SMEM_BYTES>>>();
    k_gemm2<<<dim3(NTOK / 128, HDIM / 128, NGRP), 128, SMEM_BYTES>>>();
    k_combine<<<(NTOK * (HDIM / 4)) / 256, 256>>>(out);
}

// round 17
// speedup vs baseline: 1.1036x; 1.0098x over previous
#include <cuda_runtime.h>
#include <cuda_fp16.h>
#include <math.h>
#include <stdint.h>

#define HDIM  1024
#define IDIM  2816
#define TWOI  5632
#define NEXP  8
#define NTOK  2048
#define NGRP  9   // 8 experts + base (group 8)

#define NSTG   4                // 4-stage cp.async pipeline (32 K each)
#define ABYTES 10240            // 128 rows x 40 halves x 2B (row stride 80B)
#define BROWB  272              // B smem row stride bytes (128 halves data + pad)
#define BBYTES (32 * BROWB)     // 8704
#define SMEM_BYTES (NSTG * (ABYTES + BBYTES))   // 75776 -> 2 CTAs/SM

// ---------------- scratch (device globals; no allocation) ----------------
__device__ int    g_cnt[NGRP];
__device__ int    g_tok[NGRP * NTOK];
__device__ int    g_te[NTOK * 2];
__device__ int    g_tp[NTOK * 2];
__device__ float  g_tw[NTOK * 2];
__device__ __half g_act[(size_t)NGRP * NTOK * IDIM];
__device__ float  g_y  [(size_t)NGRP * NTOK * HDIM];

// fp16 copies (converted once per launch; deterministic)
__device__ __half xh[NTOK * HDIM];
__device__ __half bwguh[HDIM * TWOI];
__device__ __half bwdh[IDIM * HDIM];
__device__ __half ewguh[(size_t)NEXP * HDIM * TWOI];
__device__ __half ewdh[(size_t)NEXP * IDIM * HDIM];

// ---------------- PTX helpers ----------------
__device__ __forceinline__ uint32_t h2u(__half2 h) { return *(uint32_t*)&h; }
__device__ __forceinline__ uint32_t sh_addr(const void* p) {
    return (uint32_t)__cvta_generic_to_shared(p);
}
#define MMA_F16(C, A, B)                                                      \
    asm volatile(                                                             \
        "mma.sync.aligned.m16n8k16.row.col.f32.f16.f16.f32 "                  \
        "{%0,%1,%2,%3}, {%4,%5,%6,%7}, {%8,%9}, {%0,%1,%2,%3};"               \
        : "+f"((C)[0]), "+f"((C)[1]), "+f"((C)[2]), "+f"((C)[3])              \
        : "r"((A)[0]), "r"((A)[1]), "r"((A)[2]), "r"((A)[3]),                 \
          "r"((B)[0]), "r"((B)[1]))
#define LDSM_X4(r0, r1, r2, r3, a)                                            \
    asm volatile("ldmatrix.sync.aligned.m8n8.x4.shared.b16 {%0,%1,%2,%3}, [%4];" \
                 : "=r"(r0), "=r"(r1), "=r"(r2), "=r"(r3) : "r"(a))
#define LDSM_X4T(r0, r1, r2, r3, a)                                           \
    asm volatile("ldmatrix.sync.aligned.m8n8.x4.trans.shared.b16 {%0,%1,%2,%3}, [%4];" \
                 : "=r"(r0), "=r"(r1), "=r"(r2), "=r"(r3) : "r"(a))
#define CP16(dst, src)                                                        \
    asm volatile("cp.async.cg.shared.global [%0], [%1], 16;" :: "r"(dst), "l"(src))
#define CP_COMMIT() asm volatile("cp.async.commit_group;" ::: "memory")
#define CP_WAIT2()  asm volatile("cp.async.wait_group 2;" ::: "memory")

// ---------------- init ----------------
__global__ void k_init() {
    if (threadIdx.x < NGRP)
        g_cnt[threadIdx.x] = (threadIdx.x == NEXP) ? NTOK : 0;
}

// ------- fused router (+x conversion) + Wgu fp32->fp16 convert -------
#define CVT_N1 (HDIM * TWOI / 8)          // base_wgu
#define CVT_N3 (NEXP * CVT_N1)            // exp_wgu
#define CVT_XW ((size_t)CVT_N1 + CVT_N3)  // 6488064 (exact /256)
#define ROUTER_BLOCKS 256
#define CVTR_BLOCKS (ROUTER_BLOCKS + (unsigned)(CVT_XW / 256))

__global__ void k_cvt_router(const float* __restrict__ x, const float* __restrict__ gw,
                             const float* __restrict__ bwgu, const float* __restrict__ ewgu) {
    if (blockIdx.x < ROUTER_BLOCKS) {
        int gtid = blockIdx.x * 256 + threadIdx.x;
        int t    = gtid >> 5;
        int lane = gtid & 31;

        const float* xr = x + (size_t)t * HDIM;
        __half* xhr = xh + (size_t)t * HDIM;
        float acc[NEXP];
#pragma unroll
        for (int e = 0; e < NEXP; e++) acc[e] = 0.f;
        for (int k = lane; k < HDIM; k += 32) {
            float xv = xr[k];
            xhr[k] = __float2half_rn(xv);
            const float4* gr = (const float4*)(gw + (size_t)k * NEXP);
            float4 g0 = gr[0], g1 = gr[1];
            acc[0] += xv * g0.x; acc[1] += xv * g0.y;
            acc[2] += xv * g0.z; acc[3] += xv * g0.w;
            acc[4] += xv * g1.x; acc[5] += xv * g1.y;
            acc[6] += xv * g1.z; acc[7] += xv * g1.w;
        }
#pragma unroll
        for (int e = 0; e < NEXP; e++) {
#pragma unroll
            for (int off = 16; off; off >>= 1)
                acc[e] += __shfl_xor_sync(0xffffffffu, acc[e], off);
        }
        if (lane == 0) {
            float m = acc[0];
#pragma unroll
            for (int e = 1; e < NEXP; e++) m = fmaxf(m, acc[e]);
            float p[NEXP];
#pragma unroll
            for (int e = 0; e < NEXP; e++) p[e] = expf(acc[e] - m);
            int i0 = 0; float b0 = p[0];
#pragma unroll
            for (int e = 1; e < NEXP; e++) if (p[e] > b0) { b0 = p[e]; i0 = e; }
            int i1 = (i0 == 0) ? 1 : 0; float b1 = p[i1];
#pragma unroll
            for (int e = 0; e < NEXP; e++)
                if (e != i0 && p[e] > b1) { b1 = p[e]; i1 = e; }
            float s = b0 + b1;
            int p0 = atomicAdd(&g_cnt[i0], 1);
            int p1 = atomicAdd(&g_cnt[i1], 1);
            g_tok[i0 * NTOK + p0] = t;
            g_tok[i1 * NTOK + p1] = t;
            g_te[2 * t + 0] = i0; g_tp[2 * t + 0] = p0; g_tw[2 * t + 0] = b0 / s;
            g_te[2 * t + 1] = i1; g_tp[2 * t + 1] = p1; g_tw[2 * t + 1] = b1 / s;
            g_tok[NEXP * NTOK + t] = t;
        }
        return;
    }
    size_t i = (size_t)(blockIdx.x - ROUTER_BLOCKS) * 256 + threadIdx.x;
    if (i >= CVT_XW) return;
    const float* s; __half* d; size_t off;
    if (i < CVT_N1) { s = bwgu; d = bwguh; off = i; }
    else            { s = ewgu; d = ewguh; off = i - CVT_N1; }
    float4 a = ((const float4*)s)[2 * off];
    float4 b = ((const float4*)s)[2 * off + 1];
    uint4 o;
    o.x = h2u(__floats2half2_rn(a.x, a.y));
    o.y = h2u(__floats2half2_rn(a.z, a.w));
    o.z = h2u(__floats2half2_rn(b.x, b.y));
    o.w = h2u(__floats2half2_rn(b.z, b.w));
    ((uint4*)d)[off] = o;
}

// ------- Wd fp32->fp16 convert (runs on side stream, overlaps gemm1) -------
#define WD_N2 (IDIM * HDIM / 8)           // base_wd
#define WD_N4 (NEXP * WD_N2)              // exp_wd
#define WD_TOTAL ((size_t)WD_N2 + WD_N4)  // 3244032 (exact /256)
#define WD_BLOCKS ((unsigned)(WD_TOTAL / 256))

__global__ void k_cvt_wd(const float* __restrict__ bwd, const float* __restrict__ ewd) {
    size_t i = (size_t)blockIdx.x * 256 + threadIdx.x;
    const float* s; __half* d; size_t off;
    if (i < WD_N2) { s = bwd; d = bwdh; off = i; }
    else           { s = ewd; d = ewdh; off = i - WD_N2; }
    float4 a = ((const float4*)s)[2 * off];
    float4 b = ((const float4*)s)[2 * off + 1];
    uint4 o;
    o.x = h2u(__floats2half2_rn(a.x, a.y));
    o.y = h2u(__floats2half2_rn(a.z, a.w));
    o.z = h2u(__floats2half2_rn(b.x, b.y));
    o.w = h2u(__floats2half2_rn(b.z, b.w));
    ((uint4*)d)[off] = o;
}

// ============================================================================
// GEMM1: act = silu(x@Wg) * (x@Wu). 4-stage cp.async, cross-stage frag pipe,
// issueA hoisted, unroll 2. Block 128 rows x 64 act-cols. (Round-16 verified.)
// ============================================================================
__global__ __launch_bounds__(128, 2) void k_gemm1() {
    int g   = blockIdx.z;
    int cnt = g_cnt[g];
    int m0  = blockIdx.x * 128;
    if (m0 >= cnt) return;
    int n0  = blockIdx.y * 64;
    const __half* W = (g == NEXP) ? bwguh : (ewguh + (size_t)g * HDIM * TWOI);

    extern __shared__ char smraw[];
    uint32_t sb = sh_addr(smraw);
    __shared__ int stok[128];

    int tid = threadIdx.x, wid = tid >> 5, lane = tid & 31;
    int wm = wid & 1, wn = wid >> 1;
    int qg = lane >> 2, qq = lane & 3;

    { int r = m0 + tid; stok[tid] = g_tok[g * NTOK + ((r < cnt) ? r : cnt - 1)]; }
    __syncthreads();

    int arow = tid >> 2, aq = tid & 3;
    const __half* asrc[4];
#pragma unroll
    for (int j = 0; j < 4; j++)
        asrc[j] = xh + (size_t)stok[arow + 32 * j] * HDIM + aq * 8;
    uint32_t adst = (uint32_t)(arow * 80 + aq * 16);
    int bk = tid >> 4, bnc = tid & 15;
    size_t bcol = (bnc < 8) ? (size_t)(n0 + bnc * 8)
                            : ((size_t)IDIM + n0 + (bnc - 8) * 8);
    const __half* bsrc = W + (size_t)bk * TWOI + bcol;
    uint32_t bdst = (uint32_t)(bk * BROWB + bnc * 16);

    uint32_t a_off = (uint32_t)((wm * 64 + (lane & 15)) * 80 + (lane >> 4) * 16);
    uint32_t b_off = (uint32_t)((lane & 15) * BROWB + (lane >> 4) * 16);

    float acc[4][8][4];
#pragma unroll
    for (int a = 0; a < 4; a++)
#pragma unroll
        for (int b = 0; b < 8; b++)
#pragma unroll
            for (int c = 0; c < 4; c++) acc[a][b][c] = 0.f;

    auto issueA = [&](int s) {
        int kk = s * 32, sub = s & 3;
        uint32_t Ab = sb + sub * ABYTES;
#pragma unroll
        for (int j = 0; j < 4; j++) CP16(Ab + adst + j * (32 * 80), asrc[j] + kk);
    };
    auto issueB = [&](int s) {
        int kk = s * 32, sub = s & 3;
        uint32_t Bb = sb + NSTG * ABYTES + sub * BBYTES;
#pragma unroll
        for (int j = 0; j < 4; j++)
            CP16(Bb + bdst + j * (8 * BROWB), bsrc + (size_t)(kk + 8 * j) * TWOI);
    };
    auto ldfrag = [&](int s, int ks, uint32_t (&af)[4][4], uint32_t (&bf)[8][2]) {
        uint32_t Ab = sb + (s & 3) * ABYTES;
        uint32_t Bb = sb + NSTG * ABYTES + (s & 3) * BBYTES;
#pragma unroll
        for (int mt = 0; mt < 4; mt++)
            LDSM_X4(af[mt][0], af[mt][1], af[mt][2], af[mt][3],
                    Ab + a_off + mt * 1280 + ks * 32);
#pragma unroll
        for (int p = 0; p < 4; p++) {
            uint32_t na = (p < 2) ? (uint32_t)(wn * 32 + p * 16)
                                  : (uint32_t)(64 + wn * 32 + (p - 2) * 16);
            LDSM_X4T(bf[2 * p][0], bf[2 * p][1], bf[2 * p + 1][0], bf[2 * p + 1][1],
                     Bb + b_off + ks * (16 * BROWB) + na * 2);
        }
    };
    auto domma = [&](uint32_t (&af)[4][4], uint32_t (&bf)[8][2]) {
#pragma unroll
        for (int mt = 0; mt < 4; mt++)
#pragma unroll
            for (int nt = 0; nt < 8; nt++)
                MMA_F16(acc[mt][nt], af[mt], bf[nt]);
    };

    issueA(0); issueB(0); CP_COMMIT();
    issueA(1); issueB(1); CP_COMMIT();
    issueA(2); issueB(2); CP_COMMIT();

    uint32_t afA[4][4], bfA[8][2], afB[4][4], bfB[8][2];
    CP_WAIT2();
    __syncthreads();
    ldfrag(0, 0, afA, bfA);

    const int NST = HDIM / 32;   // 32
#pragma unroll 2
    for (int s = 0; s < NST; s++) {
        if (s + 3 < NST) issueA(s + 3);
        ldfrag(s, 1, afB, bfB);
        domma(afA, bfA);
        if (s + 3 < NST) issueB(s + 3);
        CP_COMMIT();
        if (s + 1 < NST) {
            CP_WAIT2();
            __syncthreads();
            ldfrag(s + 1, 0, afA, bfA);
        }
        domma(afB, bfB);
    }

#pragma unroll
    for (int mt = 0; mt < 4; mt++) {
        int r0 = m0 + wm * 64 + mt * 16 + qg;
#pragma unroll
        for (int nt = 0; nt < 4; nt++) {
            int c = n0 + wn * 32 + 8 * nt + 2 * qq;
            float gv0 = acc[mt][nt][0], gv1 = acc[mt][nt][1];
            float uv0 = acc[mt][nt + 4][0], uv1 = acc[mt][nt + 4][1];
            *(__half2*)&g_act[((size_t)g * NTOK + r0) * IDIM + c] =
                __floats2half2_rn(uv0 * (gv0 / (1.f + expf(-gv0))),
                                  uv1 * (gv1 / (1.f + expf(-gv1))));
            float gv2 = acc[mt][nt][2], gv3 = acc[mt][nt][3];
            float uv2 = acc[mt][nt + 4][2], uv3 = acc[mt][nt + 4][3];
            *(__half2*)&g_act[((size_t)g * NTOK + r0 + 8) * IDIM + c] =
                __floats2half2_rn(uv2 * (gv2 / (1.f + expf(-gv2))),
                                  uv3 * (gv3 / (1.f + expf(-gv3))));
        }
    }
}

// ============================================================================
// GEMM2: y = act(half) @ Wd. Same pipeline. Block 128x128. (Round-16 verified.)
// ============================================================================
__global__ __launch_bounds__(128, 2) void k_gemm2() {
    int g   = blockIdx.z;
    int cnt = g_cnt[g];
    int m0  = blockIdx.x * 128;
    if (m0 >= cnt) return;
    int n0  = blockIdx.y * 128;
    const __half* W = (g == NEXP) ? bwdh : (ewdh + (size_t)g * IDIM * HDIM);

    extern __shared__ char smraw[];
    uint32_t sb = sh_addr(smraw);

    int tid = threadIdx.x, wid = tid >> 5, lane = tid & 31;
    int wm = wid & 1, wn = wid >> 1;
    int qg = lane >> 2, qq = lane & 3;

    int arow = tid >> 2, aq = tid & 3;
    const __half* asrc = g_act + ((size_t)g * NTOK + m0 + arow) * IDIM + aq * 8;
    uint32_t adst = (uint32_t)(arow * 80 + aq * 16);
    int bk = tid >> 4, bnc = tid & 15;
    const __half* bsrc = W + (size_t)bk * HDIM + n0 + bnc * 8;
    uint32_t bdst = (uint32_t)(bk * BROWB + bnc * 16);

    uint32_t a_off = (uint32_t)((wm * 64 + (lane & 15)) * 80 + (lane >> 4) * 16);
    uint32_t b_off = (uint32_t)((lane & 15) * BROWB + (lane >> 4) * 16);

    float acc[4][8][4];
#pragma unroll
    for (int a = 0; a < 4; a++)
#pragma unroll
        for (int b = 0; b < 8; b++)
#pragma unroll
            for (int c = 0; c < 4; c++) acc[a][b][c] = 0.f;

    auto issueA = [&](int s) {
        int kk = s * 32, sub = s & 3;
        uint32_t Ab = sb + sub * ABYTES;
#pragma unroll
        for (int j = 0; j < 4; j++)
            CP16(Ab + adst + j * (32 * 80), asrc + (size_t)(32 * j) * IDIM + kk);
    };
    auto issueB = [&](int s) {
        int kk = s * 32, sub = s & 3;
        uint32_t Bb = sb + NSTG * ABYTES + sub * BBYTES;
#pragma unroll
        for (int j = 0; j < 4; j++)
            CP16(Bb + bdst + j * (8 * BROWB), bsrc + (size_t)(kk + 8 * j) * HDIM);
    };
    auto ldfrag = [&](int s, int ks, uint32_t (&af)[4][4], uint32_t (&bf)[8][2]) {
        uint32_t Ab = sb + (s & 3) * ABYTES;
        uint32_t Bb = sb + NSTG * ABYTES + (s & 3) * BBYTES;
#pragma unroll
        for (int mt = 0; mt < 4; mt++)
            LDSM_X4(af[mt][0], af[mt][1], af[mt][2], af[mt][3],
                    Ab + a_off + mt * 1280 + ks * 32);
#pragma unroll
        for (int p = 0; p < 4; p++) {
            uint32_t na = (uint32_t)(wn * 64 + p * 16);
            LDSM_X4T(bf[2 * p][0], bf[2 * p][1], bf[2 * p + 1][0], bf[2 * p + 1][1],
                     Bb + b_off + ks * (16 * BROWB) + na * 2);
        }
    };
    auto domma = [&](uint32_t (&af)[4][4], uint32_t (&bf)[8][2]) {
#pragma unroll
        for (int mt = 0; mt < 4; mt++)
#pragma unroll
            for (int nt = 0; nt < 8; nt++)
                MMA_F16(acc[mt][nt], af[mt], bf[nt]);
    };

    issueA(0); issueB(0); CP_COMMIT();
    issueA(1); issueB(1); CP_COMMIT();
    issueA(2); issueB(2); CP_COMMIT();

    uint32_t afA[4][4], bfA[8][2], afB[4][4], bfB[8][2];
    CP_WAIT2();
    __syncthreads();
    ldfrag(0, 0, afA, bfA);

    const int NST = IDIM / 32;   // 88
#pragma unroll 2
    for (int s = 0; s < NST; s++) {
        if (s + 3 < NST) issueA(s + 3);
        ldfrag(s, 1, afB, bfB);
        domma(afA, bfA);
        if (s + 3 < NST) issueB(s + 3);
        CP_COMMIT();
        if (s + 1 < NST) {
            CP_WAIT2();
            __syncthreads();
            ldfrag(s + 1, 0, afA, bfA);
        }
        domma(afB, bfB);
    }

#pragma unroll
    for (int mt = 0; mt < 4; mt++) {
        int r0 = m0 + wm * 64 + mt * 16 + qg;
#pragma unroll
        for (int nt = 0; nt < 8; nt++) {
            int c = n0 + wn * 64 + 8 * nt + 2 * qq;
            *(float2*)&g_y[((size_t)g * NTOK + r0) * HDIM + c] =
                make_float2(acc[mt][nt][0], acc[mt][nt][1]);
            *(float2*)&g_y[((size_t)g * NTOK + r0 + 8) * HDIM + c] =
                make_float2(acc[mt][nt][2], acc[mt][nt][3]);
        }
    }
}

// ---------------- combine ----------------
__global__ void k_combine(float* __restrict__ out) {
    int idx = blockIdx.x * blockDim.x + threadIdx.x;
    int t  = idx >> 8;
    int h4 = (idx & 255) << 2;
    if (t >= NTOK) return;

    int   e0 = g_te[2 * t + 0], p0 = g_tp[2 * t + 0];
    int   e1 = g_te[2 * t + 1], p1 = g_tp[2 * t + 1];
    float w0 = g_tw[2 * t + 0], w1 = g_tw[2 * t + 1];

    float4 yb = *(const float4*)&g_y[((size_t)NEXP * NTOK + t ) * HDIM + h4];
    float4 y0 = *(const float4*)&g_y[((size_t)e0   * NTOK + p0) * HDIM + h4];
    float4 y1 = *(const float4*)&g_y[((size_t)e1   * NTOK + p1) * HDIM + h4];

    float4 o;
    o.x = yb.x + w0 * y0.x + w1 * y1.x;
    o.y = yb.y + w0 * y0.y + w1 * y1.y;
    o.z = yb.z + w0 * y0.z + w1 * y1.z;
    o.w = yb.w + w0 * y0.w + w1 * y1.w;
    *(float4*)&out[(size_t)t * HDIM + h4] = o;
}

// ---------------- launch ----------------
extern "C" void kernel_launch(void* const* d_in, const int* in_sizes, int n_in,
                              void* d_out, int out_size) {
    const float* x        = (const float*)d_in[0];
    const float* gate_w   = (const float*)d_in[1];
    const float* base_wgu = (const float*)d_in[2];
    const float* base_wd  = (const float*)d_in[3];
    const float* exp_wgu  = (const float*)d_in[4];
    const float* exp_wd   = (const float*)d_in[5];
    float* out = (float*)d_out;

    cudaFuncSetAttribute(k_gemm1, cudaFuncAttributeMaxDynamicSharedMemorySize, SMEM_BYTES);
    cudaFuncSetAttribute(k_gemm2, cudaFuncAttributeMaxDynamicSharedMemorySize, SMEM_BYTES);

    // Side stream + events for fork-join overlap of Wd conversion with gemm1.
    // Created per call (not destroyed: they remain referenced by the capture;
    // no device memory involved).
    cudaStream_t s2;
    cudaStreamCreateWithFlags(&s2, cudaStreamNonBlocking);
    cudaEvent_t evF, evJ;
    cudaEventCreateWithFlags(&evF, cudaEventDisableTiming);
    cudaEventCreateWithFlags(&evJ, cudaEventDisableTiming);

    k_init<<<1, 32>>>();
    k_cvt_router<<<CVTR_BLOCKS, 256>>>(x, gate_w, base_wgu, exp_wgu);

    // fork: Wd conversion on side stream, concurrent with gemm1
    cudaEventRecord(evF, 0);
    cudaStreamWaitEvent(s2, evF, 0);
    k_cvt_wd<<<WD_BLOCKS, 256, 0, s2>>>(base_wd, exp_wd);
    cudaEventRecord(evJ, s2);

    k_gemm1<<<dim3(NTOK / 128, IDIM / 64, NGRP), 128, SMEM_BYTES>>>();

    // join: gemm2 needs bwdh/ewdh
    cudaStreamWaitEvent(0, evJ, 0);
    k_gemm2<<<dim3(NTOK / 128, HDIM / 128, NGRP), 128, SMEM_BYTES>>>();
    k_combine<<<(NTOK * (HDIM / 4)) / 256, 256>>>(out);
}